// round 6
// baseline (speedup 1.0000x reference)
#include <cuda_runtime.h>

// Batched Kalman filter + forecast. B=16384 rows, T=504 (336 filter + 168 fcst).
// One WARP per block (32 rows), 512 blocks. 3-stage cp.async pipeline of
// 24-step tiles; smem row stride 28 floats -> conflict-free LDS.128.
// T_obs tiles skipped in forecast phase. P_update = K*R (exact algebraic
// collapse of Joseph form with K = Pp/S).

#define TTOT   504
#define LHIST  336
#define HFCST  168
#define TILE   24
#define NTILES 21     // 504/24
#define FTILES 14     // 336/24
#define RPB    32     // rows per block == threads per block (one warp)
#define SROW   28     // smem floats per row (24 data + 4 pad)
#define SARR   (RPB*SROW)              // 896 floats per array per stage
#define PIPE   3
#define SIN_FLOATS  (PIPE*5*SARR)      // 13440
#define SOUT_FLOATS (2*SARR)           // 1792
#define SMEM_BYTES  ((SIN_FLOATS + SOUT_FLOATS)*4)   // 60928 B

#define EL(v,i) ((i)==0?(v).x:((i)==1?(v).y:((i)==2?(v).z:(v).w)))

__global__ __launch_bounds__(RPB)
void kf_kernel(const float* __restrict__ T_obs,
               const float* __restrict__ T_air,
               const float* __restrict__ wind,
               const float* __restrict__ par,
               const float* __restrict__ dtv,
               const float* __restrict__ k_raw_p,
               const float* __restrict__ log_q_p,
               const float* __restrict__ log_r_p,
               const float* __restrict__ log_p0_p,
               const float* __restrict__ log_qs_p,
               const float* __restrict__ tpl_p,
               const float* __restrict__ tpq_p,
               const float* __restrict__ twc_p,
               const float* __restrict__ ts_p,
               const float* __restrict__ tfc_p,
               float* __restrict__ out,
               int B)
{
    extern __shared__ float smem[];
    float* sin   = smem;                    // [PIPE][5][SARR]
    float* soutT = smem + SIN_FLOATS;
    float* soutV = soutT + SARR;

    const int tid  = threadIdx.x;
    const int row0 = blockIdx.x * RPB;

    const float* arrs[5] = {T_obs, T_air, wind, par, dtv};

    // cooperative coalesced tile loader; a0=0 loads all 5 arrays, a0=1 skips T_obs
    auto issue_tile = [&](int tile, int buf, int a0) {
        for (int a = a0; a < 5; a++) {
            const float* gb = arrs[a];
            #pragma unroll
            for (int it = 0; it < 6; it++) {
                int q = tid + it * RPB;            // 0..191
                int r = q / 6, j = q - r * 6;      // row, 16B chunk
                const float* g = gb + (size_t)(row0 + r) * TTOT + tile * TILE + j * 4;
                float* ds = sin + (buf * 5 + a) * SARR + r * SROW + j * 4;
                unsigned du = (unsigned)__cvta_generic_to_shared(ds);
                asm volatile("cp.async.cg.shared.global [%0], [%1], 16;\n" :: "r"(du), "l"(g));
            }
        }
        asm volatile("cp.async.commit_group;\n");
    };

    // prefetch PIPE tiles, overlapping with scalar param math below
    issue_tile(0, 0, 0);
    issue_tile(1, 1, 0);
    issue_tile(2, 2, 0);

    const float k   = log1pf(expf(__ldg(k_raw_p)));
    const float qq  = expf(__ldg(log_qs_p)) * expf(__ldg(log_q_p));
    const float R   = expf(__ldg(log_r_p));
    const float P0  = expf(__ldg(log_p0_p));
    const float tpl = __ldg(tpl_p);
    const float tpq = __ldg(tpq_p);
    const float twc = __ldg(twc_p);
    const float ts  = __ldg(ts_p);
    const float tfc = __ldg(tfc_p);

    float s = 0.0f, P = P0;
    float pTa = 0.0f, pw = 0.0f, pp = 0.0f;

    for (int tile = 0; tile < NTILES; ++tile) {
        const int buf = tile % PIPE;
        asm volatile("cp.async.wait_group %0;\n" :: "n"(PIPE - 1) : "memory");
        __syncwarp();                          // tile data visible to all lanes

        const float* by  = sin + (buf * 5 + 0) * SARR + tid * SROW;
        const float* bta = by  + SARR;
        const float* bw  = bta + SARR;
        const float* bp  = bw  + SARR;
        const float* bd  = bp  + SARR;

        if (tile < FTILES) {
            #pragma unroll
            for (int g = 0; g < 6; g++) {
                float4 y4 = *(const float4*)(by  + g * 4);
                float4 t4 = *(const float4*)(bta + g * 4);
                float4 w4 = *(const float4*)(bw  + g * 4);
                float4 p4 = *(const float4*)(bp  + g * 4);
                float4 d4 = *(const float4*)(bd  + g * 4);
                #pragma unroll
                for (int i = 0; i < 4; i++) {
                    float yv = EL(y4,i), tav = EL(t4,i), wv = EL(w4,i),
                          pv = EL(p4,i), dv = EL(d4,i);
                    if (!(tile == 0 && g == 0 && i == 0)) {
                        float dtt = fmaxf(dv, 1.0f);
                        float dT  = s - pTa;
                        float cl  = tpl * pp + tpq * pp * pp + twc * pw
                                  + ts * dT + tfc * pw * dT;
                        float Tp  = s + (cl - k * dT) * dtt;
                        Tp = fminf(fmaxf(Tp, -50.0f), 100.0f);
                        float F = 1.0f + ((ts + tfc * pw) - k) * dtt;
                        F = fminf(fmaxf(F, -2.0f), 2.0f);
                        float Pp = F * F * P + qq * dtt;
                        Pp = fminf(fmaxf(Pp, 1e-10f), 1e6f);
                        float K = __fdividef(Pp, Pp + R);
                        s = Tp + K * (yv - Tp);
                        P = K * R;
                    } else {
                        s = yv;
                    }
                    pTa = tav; pw = wv; pp = pv;
                }
            }
            __syncwarp();                      // reads done before buf refill
            if (tile + PIPE < NTILES)
                issue_tile(tile + PIPE, buf, (tile + PIPE >= FTILES) ? 1 : 0);
        } else {
            #pragma unroll
            for (int g = 0; g < 6; g++) {
                float4 t4 = *(const float4*)(bta + g * 4);
                float4 w4 = *(const float4*)(bw  + g * 4);
                float4 p4 = *(const float4*)(bp  + g * 4);
                float4 d4 = *(const float4*)(bd  + g * 4);
                float oT[4], oV[4];
                #pragma unroll
                for (int i = 0; i < 4; i++) {
                    float tav = EL(t4,i), wv = EL(w4,i), pv = EL(p4,i), dv = EL(d4,i);
                    float dtt = fmaxf(dv, 1.0f);
                    float dT  = s - pTa;
                    float cl  = tpl * pp + tpq * pp * pp + twc * pw
                              + ts * dT + tfc * pw * dT;
                    float Tp  = s + (cl - k * dT) * dtt;
                    Tp = fminf(fmaxf(Tp, -50.0f), 100.0f);
                    float F = 1.0f + ((ts + tfc * pw) - k) * dtt;
                    F = fminf(fmaxf(F, -2.0f), 2.0f);
                    float Pp = F * F * P + qq * dtt;
                    Pp = fminf(fmaxf(Pp, 1e-10f), 1e6f);
                    s = Tp; P = Pp;
                    oT[i] = Tp; oV[i] = Pp;
                    pTa = tav; pw = wv; pp = pv;
                }
                *(float4*)(soutT + tid * SROW + g * 4) = make_float4(oT[0], oT[1], oT[2], oT[3]);
                *(float4*)(soutV + tid * SROW + g * 4) = make_float4(oV[0], oV[1], oV[2], oV[3]);
            }
            __syncwarp();                      // buf reads + sout writes done
            if (tile + PIPE < NTILES)
                issue_tile(tile + PIPE, buf, 1);
            // coalesced flush of staged outputs
            const int h0 = (tile - FTILES) * TILE;
            #pragma unroll
            for (int it = 0; it < 6; it++) {
                int q = tid + it * RPB;
                int r = q / 6, j = q - r * 6;
                size_t o = (size_t)(row0 + r) * HFCST + h0 + j * 4;
                *(float4*)(out + o) = *(const float4*)(soutT + r * SROW + j * 4);
                *(float4*)(out + (size_t)B * HFCST + o) = *(const float4*)(soutV + r * SROW + j * 4);
            }
            // next iteration's top __syncwarp orders sout reuse
        }
    }
}

extern "C" void kernel_launch(void* const* d_in, const int* in_sizes, int n_in,
                              void* d_out, int out_size) {
    const float* T_obs = (const float*)d_in[0];
    const float* T_air = (const float*)d_in[1];
    const float* wind  = (const float*)d_in[2];
    const float* par   = (const float*)d_in[3];
    const float* dtv   = (const float*)d_in[4];
    // d_in[5] = L_hist (compile-time constant 336)
    const float* k_raw  = (const float*)d_in[6];
    const float* log_q  = (const float*)d_in[7];
    const float* log_r  = (const float*)d_in[8];
    const float* log_p0 = (const float*)d_in[9];
    const float* log_qs = (const float*)d_in[10];
    const float* tpl = (const float*)d_in[11];
    const float* tpq = (const float*)d_in[12];
    const float* twc = (const float*)d_in[13];
    const float* ts_ = (const float*)d_in[14];
    const float* tfc = (const float*)d_in[15];

    int B = in_sizes[0] / TTOT;
    cudaFuncSetAttribute(kf_kernel, cudaFuncAttributeMaxDynamicSharedMemorySize, SMEM_BYTES);
    int blocks = (B + RPB - 1) / RPB;
    kf_kernel<<<blocks, RPB, SMEM_BYTES>>>(T_obs, T_air, wind, par, dtv,
                                           k_raw, log_q, log_r, log_p0, log_qs,
                                           tpl, tpq, twc, ts_, tfc,
                                           (float*)d_out, B);
}

// round 7
// speedup vs baseline: 1.1315x; 1.1315x over previous
#include <cuda_runtime.h>

// Batched Kalman filter + forecast. B=16384 rows, T=504 (336 filter + 168 fcst).
// 64 threads/block (2 warps) x 256 blocks: 2 blocks/SM, single wave, all 512
// warps resident. 12-step tiles, 4-stage cp.async pipeline -> 3 tiles in
// flight during compute. smem row stride 20 floats (5x16B, odd) -> conflict-
// free LDS.128/STS.128. T_obs skipped in forecast tiles.
// P_update = (1-K)^2*Pp + K^2*R == K*R exactly (K = Pp/S, 1-K = R/S).

#define TTOT   504
#define LHIST  336
#define HFCST  168
#define TILE   12
#define NTILES 42     // 504/12
#define FTILES 28     // 336/12
#define RPB    64     // rows per block == threads per block (2 warps)
#define SROW   20     // smem floats per row (12 data + 8 pad; 5 x 16B groups)
#define SARR   (RPB*SROW)              // 1280 floats per array per stage
#define PIPE   4
#define CHK    (TILE/4)                // 3 x 16B chunks per row per tile
#define SIN_FLOATS  (PIPE*5*SARR)      // 25600
#define SOUT_FLOATS (2*SARR)           // 2560
#define SMEM_BYTES  ((SIN_FLOATS + SOUT_FLOATS)*4)   // 112640 B (2 blocks/SM)

#define EL(v,i) ((i)==0?(v).x:((i)==1?(v).y:((i)==2?(v).z:(v).w)))

__global__ __launch_bounds__(RPB)
void kf_kernel(const float* __restrict__ T_obs,
               const float* __restrict__ T_air,
               const float* __restrict__ wind,
               const float* __restrict__ par,
               const float* __restrict__ dtv,
               const float* __restrict__ k_raw_p,
               const float* __restrict__ log_q_p,
               const float* __restrict__ log_r_p,
               const float* __restrict__ log_p0_p,
               const float* __restrict__ log_qs_p,
               const float* __restrict__ tpl_p,
               const float* __restrict__ tpq_p,
               const float* __restrict__ twc_p,
               const float* __restrict__ ts_p,
               const float* __restrict__ tfc_p,
               float* __restrict__ out,
               int B)
{
    extern __shared__ float smem[];
    float* sin   = smem;                    // [PIPE][5][SARR]
    float* soutT = smem + SIN_FLOATS;
    float* soutV = soutT + SARR;

    const int tid  = threadIdx.x;
    const int row0 = blockIdx.x * RPB;

    const float* arrs[5] = {T_obs, T_air, wind, par, dtv};

    // cooperative coalesced tile loader; a0=1 skips T_obs (forecast tiles)
    auto issue_tile = [&](int tile, int buf, int a0) {
        for (int a = a0; a < 5; a++) {
            const float* gb = arrs[a];
            #pragma unroll
            for (int it = 0; it < CHK; it++) {
                int q = tid + it * RPB;            // 0..191
                int r = q / CHK, j = q - r * CHK;  // row, 16B chunk
                const float* g = gb + (size_t)(row0 + r) * TTOT + tile * TILE + j * 4;
                float* ds = sin + (buf * 5 + a) * SARR + r * SROW + j * 4;
                unsigned du = (unsigned)__cvta_generic_to_shared(ds);
                asm volatile("cp.async.cg.shared.global [%0], [%1], 16;\n" :: "r"(du), "l"(g));
            }
        }
        asm volatile("cp.async.commit_group;\n");
    };

    // prefetch PIPE tiles; scalar param math overlaps the first waits
    issue_tile(0, 0, 0);
    issue_tile(1, 1, 0);
    issue_tile(2, 2, 0);
    issue_tile(3, 3, 0);

    const float k   = log1pf(expf(__ldg(k_raw_p)));
    const float qq  = expf(__ldg(log_qs_p)) * expf(__ldg(log_q_p));
    const float R   = expf(__ldg(log_r_p));
    const float P0  = expf(__ldg(log_p0_p));
    const float tpl = __ldg(tpl_p);
    const float tpq = __ldg(tpq_p);
    const float twc = __ldg(twc_p);
    const float ts  = __ldg(ts_p);
    const float tfc = __ldg(tfc_p);

    float s = 0.0f, P = P0;
    float pTa = 0.0f, pw = 0.0f, pp = 0.0f;

    for (int tile = 0; tile < NTILES; ++tile) {
        const int buf = tile & (PIPE - 1);
        asm volatile("cp.async.wait_group %0;\n" :: "n"(PIPE - 1) : "memory");
        __syncthreads();                       // tile data ready; buf consumable

        const float* by  = sin + (buf * 5 + 0) * SARR + tid * SROW;
        const float* bta = by  + SARR;
        const float* bw  = bta + SARR;
        const float* bp  = bw  + SARR;
        const float* bd  = bp  + SARR;

        if (tile < FTILES) {
            // ---------------- filter phase ----------------
            #pragma unroll
            for (int g = 0; g < CHK; g++) {
                float4 y4 = *(const float4*)(by  + g * 4);
                float4 t4 = *(const float4*)(bta + g * 4);
                float4 w4 = *(const float4*)(bw  + g * 4);
                float4 p4 = *(const float4*)(bp  + g * 4);
                float4 d4 = *(const float4*)(bd  + g * 4);
                #pragma unroll
                for (int i = 0; i < 4; i++) {
                    float yv = EL(y4,i), tav = EL(t4,i), wv = EL(w4,i),
                          pv = EL(p4,i), dv = EL(d4,i);
                    if (!(tile == 0 && g == 0 && i == 0)) {
                        float dtt = fmaxf(dv, 1.0f);
                        float dT  = s - pTa;
                        float cl  = tpl * pp + tpq * pp * pp + twc * pw
                                  + ts * dT + tfc * pw * dT;
                        float Tp  = s + (cl - k * dT) * dtt;
                        Tp = fminf(fmaxf(Tp, -50.0f), 100.0f);
                        float F = 1.0f + ((ts + tfc * pw) - k) * dtt;
                        F = fminf(fmaxf(F, -2.0f), 2.0f);
                        float Pp = F * F * P + qq * dtt;
                        Pp = fminf(fmaxf(Pp, 1e-10f), 1e6f);
                        float K = __fdividef(Pp, Pp + R);
                        s = Tp + K * (yv - Tp);
                        P = K * R;
                    } else {
                        s = yv;
                    }
                    pTa = tav; pw = wv; pp = pv;
                }
            }
            __syncthreads();                   // all reads of buf done
            if (tile + PIPE < NTILES)
                issue_tile(tile + PIPE, buf, (tile + PIPE >= FTILES) ? 1 : 0);
        } else {
            // ---------------- forecast phase ----------------
            #pragma unroll
            for (int g = 0; g < CHK; g++) {
                float4 t4 = *(const float4*)(bta + g * 4);
                float4 w4 = *(const float4*)(bw  + g * 4);
                float4 p4 = *(const float4*)(bp  + g * 4);
                float4 d4 = *(const float4*)(bd  + g * 4);
                float oT[4], oV[4];
                #pragma unroll
                for (int i = 0; i < 4; i++) {
                    float tav = EL(t4,i), wv = EL(w4,i), pv = EL(p4,i), dv = EL(d4,i);
                    float dtt = fmaxf(dv, 1.0f);
                    float dT  = s - pTa;
                    float cl  = tpl * pp + tpq * pp * pp + twc * pw
                              + ts * dT + tfc * pw * dT;
                    float Tp  = s + (cl - k * dT) * dtt;
                    Tp = fminf(fmaxf(Tp, -50.0f), 100.0f);
                    float F = 1.0f + ((ts + tfc * pw) - k) * dtt;
                    F = fminf(fmaxf(F, -2.0f), 2.0f);
                    float Pp = F * F * P + qq * dtt;
                    Pp = fminf(fmaxf(Pp, 1e-10f), 1e6f);
                    s = Tp; P = Pp;
                    oT[i] = Tp; oV[i] = Pp;
                    pTa = tav; pw = wv; pp = pv;
                }
                *(float4*)(soutT + tid * SROW + g * 4) = make_float4(oT[0], oT[1], oT[2], oT[3]);
                *(float4*)(soutV + tid * SROW + g * 4) = make_float4(oV[0], oV[1], oV[2], oV[3]);
            }
            __syncthreads();                   // buf reads + sout writes done
            if (tile + PIPE < NTILES)
                issue_tile(tile + PIPE, buf, 1);
            // coalesced flush of staged outputs
            const int h0 = (tile - FTILES) * TILE;
            #pragma unroll
            for (int it = 0; it < CHK; it++) {
                int q = tid + it * RPB;
                int r = q / CHK, j = q - r * CHK;
                size_t o = (size_t)(row0 + r) * HFCST + h0 + j * 4;
                *(float4*)(out + o) = *(const float4*)(soutT + r * SROW + j * 4);
                *(float4*)(out + (size_t)B * HFCST + o) = *(const float4*)(soutV + r * SROW + j * 4);
            }
            // next iteration's top __syncthreads orders sout reuse
        }
    }
}

extern "C" void kernel_launch(void* const* d_in, const int* in_sizes, int n_in,
                              void* d_out, int out_size) {
    const float* T_obs = (const float*)d_in[0];
    const float* T_air = (const float*)d_in[1];
    const float* wind  = (const float*)d_in[2];
    const float* par   = (const float*)d_in[3];
    const float* dtv   = (const float*)d_in[4];
    // d_in[5] = L_hist (compile-time constant 336)
    const float* k_raw  = (const float*)d_in[6];
    const float* log_q  = (const float*)d_in[7];
    const float* log_r  = (const float*)d_in[8];
    const float* log_p0 = (const float*)d_in[9];
    const float* log_qs = (const float*)d_in[10];
    const float* tpl = (const float*)d_in[11];
    const float* tpq = (const float*)d_in[12];
    const float* twc = (const float*)d_in[13];
    const float* ts_ = (const float*)d_in[14];
    const float* tfc = (const float*)d_in[15];

    int B = in_sizes[0] / TTOT;
    cudaFuncSetAttribute(kf_kernel, cudaFuncAttributeMaxDynamicSharedMemorySize, SMEM_BYTES);
    int blocks = (B + RPB - 1) / RPB;
    kf_kernel<<<blocks, RPB, SMEM_BYTES>>>(T_obs, T_air, wind, par, dtv,
                                           k_raw, log_q, log_r, log_p0, log_qs,
                                           tpl, tpq, twc, ts_, tfc,
                                           (float*)d_out, B);
}